// round 16
// baseline (speedup 1.0000x reference)
#include <cuda_runtime.h>
#include <math.h>

#define NMAX 100000
#define EMAX 1600000

typedef unsigned int u32;
typedef unsigned long long u64;

// ---------------- PTX helpers ----------------
__device__ __forceinline__ u64 pk2(float x, float y) {
    u64 r; asm("mov.b64 %0, {%1,%2};" : "=l"(r) : "f"(x), "f"(y)); return r;
}
__device__ __forceinline__ float2 upk2(u64 v) {
    float2 r; asm("mov.b64 {%0,%1}, %2;" : "=f"(r.x), "=f"(r.y) : "l"(v)); return r;
}
__device__ __forceinline__ void fma2(u64& d, u64 a, u64 b) {
    asm("fma.rn.f32x2 %0, %1, %2, %0;" : "+l"(d) : "l"(a), "l"(b));
}
__device__ __forceinline__ u32 tf32of(float x) {
    u32 r; asm("cvt.rna.tf32.f32 %0, %1;" : "=r"(r) : "f"(x)); return r;
}
__device__ __forceinline__ float tf32f(float x) {
    u32 r; asm("cvt.rna.tf32.f32 %0, %1;" : "=r"(r) : "f"(x)); return __uint_as_float(r);
}
__device__ __forceinline__ void mma_tf32(float* c, u32 a0, u32 a1, u32 a2, u32 a3,
                                         u32 b0, u32 b1) {
    asm volatile("mma.sync.aligned.m16n8k8.row.col.f32.tf32.tf32.f32 "
                 "{%0,%1,%2,%3},{%4,%5,%6,%7},{%8,%9},{%0,%1,%2,%3};"
                 : "+f"(c[0]), "+f"(c[1]), "+f"(c[2]), "+f"(c[3])
                 : "r"(a0), "r"(a1), "r"(a2), "r"(a3), "r"(b0), "r"(b1));
}
__device__ __forceinline__ void red4(float* p, float a, float b, float c, float d) {
    asm volatile("red.global.v4.f32.add [%0], {%1,%2,%3,%4};"
                 :: "l"(p), "f"(a), "f"(b), "f"(c), "f"(d) : "memory");
}
__device__ __forceinline__ void cp16(u32 smem, const void* gmem, int bytes) {
    asm volatile("cp.async.cg.shared.global [%0], [%1], 16, %2;"
                 :: "r"(smem), "l"(gmem), "r"(bytes));
}
#define CP_COMMIT() asm volatile("cp.async.commit_group;" ::: "memory")
#define CP_WAIT1()  asm volatile("cp.async.wait_group 1;" ::: "memory")
#define CP_WAIT0()  asm volatile("cp.async.wait_group 0;" ::: "memory")

// ---------------- scratch ----------------
__device__ __align__(16) float g_q [(size_t)NMAX * 64];
__device__ __align__(16) float g_k [(size_t)NMAX * 64];
__device__ __align__(16) float g_vn[(size_t)NMAX * 64];   // v ⊙ ni
__device__ __align__(16) float g_agg[(size_t)NMAX * 64];  // unnormalized Σ exp·vn
__device__ __align__(16) float g_ssum[(size_t)NMAX * 8];
__device__ __align__(16) float g_eterm[(size_t)EMAX * 8];

// ---------------- init (split so edge_proj is the 4th launch for ncu) ----------------
__global__ void k_init_a(int N) {
    long long i = (long long)blockIdx.x * blockDim.x + threadIdx.x;
    if (i < (long long)N * 64) g_agg[i] = 0.f;
}
__global__ void k_init_b(int N) {
    long long i = (long long)blockIdx.x * blockDim.x + threadIdx.x;
    if (i < (long long)N * 8) g_ssum[i] = 0.f;
}

// ---------------- K: node LN + Q,K,V projections (f32x2), vn = v*ni ----------------
__global__ void k_node_qkv(const float* __restrict__ ns,
                           const float* __restrict__ wq, const float* __restrict__ bq,
                           const float* __restrict__ wk, const float* __restrict__ bk,
                           const float* __restrict__ wv, const float* __restrict__ bv,
                           const float* __restrict__ gg, const float* __restrict__ bb,
                           int N) {
    extern __shared__ float sm[];
    float* W  = sm;            // 3*4096
    float* B  = sm + 12288;
    float* G  = sm + 12480;
    float* Bt = sm + 12544;
    float* xs = sm + 12608;    // 8*64
    int tid = threadIdx.x;
    for (int i = tid; i < 4096; i += 256) { W[i] = wq[i]; W[4096 + i] = wk[i]; W[8192 + i] = wv[i]; }
    if (tid < 64) { B[tid] = bq[tid]; B[64 + tid] = bk[tid]; B[128 + tid] = bv[tid]; G[tid] = gg[tid]; Bt[tid] = bb[tid]; }
    __syncthreads();
    int warp = tid >> 5, lane = tid & 31;
    float* xw = xs + warp * 64;
    for (long long r = (long long)blockIdx.x * 8 + warp; r < N; r += (long long)gridDim.x * 8) {
        const float* xr = ns + r * 64;
        float x0 = xr[lane], x1 = xr[lane + 32];
        float s1 = x0 + x1, s2 = x0 * x0 + x1 * x1;
        #pragma unroll
        for (int o = 16; o; o >>= 1) {
            s1 += __shfl_xor_sync(0xffffffffu, s1, o);
            s2 += __shfl_xor_sync(0xffffffffu, s2, o);
        }
        float m = s1 * 0.015625f;
        float rs = rsqrtf(s2 * 0.015625f - m * m + 1e-5f);
        float y0 = (x0 - m) * rs * G[lane] + Bt[lane];
        float y1 = (x1 - m) * rs * G[lane + 32] + Bt[lane + 32];
        xw[lane] = y0; xw[lane + 32] = y1;
        __syncwarp();
        int c2 = 2 * lane;
        u64 aq = *(const u64*)&B[c2];
        u64 ak = *(const u64*)&B[64 + c2];
        u64 av = *(const u64*)&B[128 + c2];
        #pragma unroll 8
        for (int i = 0; i < 64; i++) {
            float xi = xw[i];
            u64 xx = pk2(xi, xi);
            fma2(aq, xx, *(const u64*)&W[i * 64 + c2]);
            fma2(ak, xx, *(const u64*)&W[4096 + i * 64 + c2]);
            fma2(av, xx, *(const u64*)&W[8192 + i * 64 + c2]);
        }
        *(float2*)&g_q[r * 64 + c2] = upk2(aq);
        *(float2*)&g_k[r * 64 + c2] = upk2(ak);
        float2 vproj = upk2(av);
        float2 vn; vn.x = vproj.x * xw[c2]; vn.y = vproj.y * xw[c2 + 1];
        *(float2*)&g_vn[r * 64 + c2] = vn;
        __syncwarp();
    }
}

// ---------------- K: edge LN + (ei@we+be)·ei per head — 64-row tiles, 2 blocks/SM --------
// smem floats: WH 4096 | B 64 | G 64 | Bt 64 | ES 2*4096 | XH 64*68 | XL 64*68 = 21184
__global__ __launch_bounds__(512, 2)
void k_edge_proj_tc(const float* __restrict__ es,
                    const float* __restrict__ we, const float* __restrict__ be,
                    const float* __restrict__ gg, const float* __restrict__ bb,
                    int E) {
    extern __shared__ float sm[];
    u32*   WH = (u32*)sm;            // 4096
    float* B  = sm + 4096;
    float* G  = sm + 4160;
    float* Bt = sm + 4224;
    float* ES = sm + 4288;           // 2*4096
    float* XH = sm + 12480;          // 64*68
    float* XL = sm + 16832;          // 64*68
    int tid = threadIdx.x;

    for (int idx = tid; idx < 2048; idx += 512) {
        int L = idx & 31, K = (idx >> 5) & 7, T = idx >> 8;
        int kk = K * 8 + (L & 3), nn = T * 8 + (L >> 2);
        WH[idx * 2]     = tf32of(we[kk * 64 + nn]);
        WH[idx * 2 + 1] = tf32of(we[(kk + 4) * 64 + nn]);
    }
    if (tid < 64) { B[tid] = be[tid]; G[tid] = gg[tid]; Bt[tid] = bb[tid]; }
    __syncthreads();

    int warp = tid >> 5, lane = tid & 31;
    int wm = warp & 3, wn = warp >> 2;          // wm: 16-row group, wn: 16-col group
    int qr = lane >> 2, qc = lane & 3;
    int r0 = 16 * wm + qr;
    long long ntiles = ((long long)E + 63) >> 6;
    long long stride = gridDim.x;
    u32 es_smem0 = (u32)__cvta_generic_to_shared(ES);

    long long t = blockIdx.x;
    if (t < ntiles) {
        long long base = t << 6;
        #pragma unroll
        for (int j = 0; j < 2; j++) {
            int idx = j * 512 + tid;               // float4 idx 0..1023
            int r = idx >> 4, c4 = (idx & 15) << 2;
            int ok = (base + r) < E ? 16 : 0;
            cp16(es_smem0 + (u32)((r * 64 + c4) * 4), &es[(base + r) * 64 + c4], ok);
        }
    }
    CP_COMMIT();

    int pb = 0;
    for (; t < ntiles; t += stride) {
        long long tn = t + stride;
        if (tn < ntiles) {
            long long basen = tn << 6;
            u32 dst = es_smem0 + (u32)((pb ^ 1) * 4096 * 4);
            #pragma unroll
            for (int j = 0; j < 2; j++) {
                int idx = j * 512 + tid;
                int r = idx >> 4, c4 = (idx & 15) << 2;
                int ok = (basen + r) < E ? 16 : 0;
                cp16(dst + (u32)((r * 64 + c4) * 4), &es[(basen + r) * 64 + c4], ok);
            }
            CP_COMMIT();
            CP_WAIT1();
        } else {
            CP_COMMIT();
            CP_WAIT0();
        }
        __syncthreads();

        long long base = t << 6;
        const float* EScur = ES + pb * 4096;
        // LN: 4 rows per warp
        #pragma unroll
        for (int r4 = 0; r4 < 4; r4++) {
            int r = warp * 4 + r4;
            float x0 = EScur[r * 64 + lane], x1 = EScur[r * 64 + lane + 32];
            float s1 = x0 + x1, s2 = x0 * x0 + x1 * x1;
            #pragma unroll
            for (int o = 16; o; o >>= 1) {
                s1 += __shfl_xor_sync(0xffffffffu, s1, o);
                s2 += __shfl_xor_sync(0xffffffffu, s2, o);
            }
            float m = s1 * 0.015625f;
            float rs = rsqrtf(s2 * 0.015625f - m * m + 1e-5f);
            float y0 = (x0 - m) * rs * G[lane] + Bt[lane];
            float y1 = (x1 - m) * rs * G[lane + 32] + Bt[lane + 32];
            float h0 = tf32f(y0), h1 = tf32f(y1);
            XH[r * 68 + lane] = h0;      XH[r * 68 + lane + 32] = h1;
            XL[r * 68 + lane] = tf32f(y0 - h0); XL[r * 68 + lane + 32] = tf32f(y1 - h1);
        }
        __syncthreads();
        float c[2][4];
        #pragma unroll
        for (int t4 = 0; t4 < 2; t4++) {
            int cc = 16 * wn + 8 * t4 + 2 * qc;
            c[t4][0] = B[cc]; c[t4][1] = B[cc + 1];
            c[t4][2] = B[cc]; c[t4][3] = B[cc + 1];
        }
        #pragma unroll
        for (int k = 0; k < 8; k++) {
            u32 ah0 = __float_as_uint(XH[r0 * 68 + 8 * k + qc]);
            u32 ah1 = __float_as_uint(XH[(r0 + 8) * 68 + 8 * k + qc]);
            u32 ah2 = __float_as_uint(XH[r0 * 68 + 8 * k + qc + 4]);
            u32 ah3 = __float_as_uint(XH[(r0 + 8) * 68 + 8 * k + qc + 4]);
            u32 al0 = __float_as_uint(XL[r0 * 68 + 8 * k + qc]);
            u32 al1 = __float_as_uint(XL[(r0 + 8) * 68 + 8 * k + qc]);
            u32 al2 = __float_as_uint(XL[r0 * 68 + 8 * k + qc + 4]);
            u32 al3 = __float_as_uint(XL[(r0 + 8) * 68 + 8 * k + qc + 4]);
            #pragma unroll
            for (int t4 = 0; t4 < 2; t4++) {
                int gidx = (((2 * wn + t4) * 8 + k) * 32 + lane) * 2;
                uint2 bh = *(const uint2*)&WH[gidx];
                mma_tf32(c[t4], ah0, ah1, ah2, ah3, bh.x, bh.y);
                mma_tf32(c[t4], al0, al1, al2, al3, bh.x, bh.y);
            }
        }
        #pragma unroll
        for (int t4 = 0; t4 < 2; t4++) {
            int cc = 16 * wn + 8 * t4 + 2 * qc;
            float e00 = XH[r0 * 68 + cc]       + XL[r0 * 68 + cc];
            float e01 = XH[r0 * 68 + cc + 1]   + XL[r0 * 68 + cc + 1];
            float e10 = XH[(r0 + 8) * 68 + cc]     + XL[(r0 + 8) * 68 + cc];
            float e11 = XH[(r0 + 8) * 68 + cc + 1] + XL[(r0 + 8) * 68 + cc + 1];
            float p0 = c[t4][0] * e00 + c[t4][1] * e01;
            float p1 = c[t4][2] * e10 + c[t4][3] * e11;
            p0 += __shfl_xor_sync(0xffffffffu, p0, 1);
            p0 += __shfl_xor_sync(0xffffffffu, p0, 2);
            p1 += __shfl_xor_sync(0xffffffffu, p1, 1);
            p1 += __shfl_xor_sync(0xffffffffu, p1, 2);
            if (qc == 0) {
                long long row = base + 16 * wm + qr;
                int hh = 2 * wn + t4;
                if (row < E)     g_eterm[row * 8 + hh] = p0;
                if (row + 8 < E) g_eterm[(row + 8) * 8 + hh] = p1;
            }
        }
        __syncthreads();
        pb ^= 1;
    }
}

// ---------------- K: att=exp(score), segment-sum, fused unnormalized aggregate -----------
__global__ void k_scores(const int* __restrict__ eidx, float* __restrict__ att, int E) {
    long long gid = (long long)blockIdx.x * blockDim.x + threadIdx.x;
    long long E8 = (long long)E * 8;
    bool act = gid < E8;
    long long e = act ? (gid >> 3) : 0;
    int h = (int)(gid & 7);
    int lane = threadIdx.x & 31;
    int s0 = 0, d0i = 0;
    if (act && h == 0) { s0 = eidx[e]; d0i = eidx[(long long)E + e]; }
    int src = __shfl_sync(0xffffffffu, s0, lane & ~7);
    int dst = __shfl_sync(0xffffffffu, d0i, lane & ~7);
    float a = 0.f;
    if (act) {
        const float4* qp = (const float4*)&g_q[(size_t)src * 64 + h * 8];
        const float4* kp = (const float4*)&g_k[(size_t)dst * 64 + h * 8];
        float4 q0 = qp[0], q1 = qp[1], k0 = kp[0], k1 = kp[1];
        float sc = q0.x * k0.x + q0.y * k0.y + q0.z * k0.z + q0.w * k0.w
                 + q1.x * k1.x + q1.y * k1.y + q1.z * k1.z + q1.w * k1.w;
        sc = (sc + g_eterm[gid]) * 0.35355339059327373f;
        a = __expf(sc);
        att[gid] = a;
        const float4* vp = (const float4*)&g_vn[(size_t)dst * 64 + h * 8];
        float4 v0 = vp[0], v1 = vp[1];
        float* p = &g_agg[(size_t)src * 64 + h * 8];
        red4(p,     a * v0.x, a * v0.y, a * v0.z, a * v0.w);
        red4(p + 4, a * v1.x, a * v1.y, a * v1.z, a * v1.w);
    }
    float b1 = __shfl_down_sync(0xffffffffu, a, 1);
    float b2 = __shfl_down_sync(0xffffffffu, a, 2);
    float b3 = __shfl_down_sync(0xffffffffu, a, 3);
    if (act && (h & 3) == 0)
        red4(&g_ssum[(size_t)src * 8 + h], a, b1, b2, b3);
}

// ---------------- K: node update + node FFN (f32x2); agg normalized at load -------------
__global__ void k_node_ffn(const float* __restrict__ ns,
                           const float* __restrict__ wno, const float* __restrict__ bno,
                           const float* __restrict__ g2, const float* __restrict__ b2,
                           const float* __restrict__ f1w, const float* __restrict__ f1b,
                           const float* __restrict__ f2w, const float* __restrict__ f2b,
                           float* __restrict__ node_out, int N) {
    extern __shared__ float sm[];
    float* Wno = sm;
    float* W1  = sm + 4096;
    float* W2  = sm + 12288;
    float* Bno = sm + 20480;
    float* B1  = sm + 20544;
    float* B2  = sm + 20672;
    float* G   = sm + 20736;
    float* Bt  = sm + 20800;
    float* xs  = sm + 20864;
    float* hs  = sm + 21376;
    int tid = threadIdx.x;
    for (int i = tid; i < 4096; i += 256) Wno[i] = wno[i];
    for (int i = tid; i < 8192; i += 256) { W1[i] = f1w[i]; W2[i] = f2w[i]; }
    if (tid < 128) B1[tid] = f1b[tid];
    if (tid < 64) { Bno[tid] = bno[tid]; B2[tid] = f2b[tid]; G[tid] = g2[tid]; Bt[tid] = b2[tid]; }
    __syncthreads();
    int warp = tid >> 5, lane = tid & 31;
    int c2 = 2 * lane;
    float* xw = xs + warp * 64;
    float* hw = hs + warp * 128;
    for (long long r = (long long)blockIdx.x * 8 + warp; r < N; r += (long long)gridDim.x * 8) {
        float den = g_ssum[r * 8 + (lane >> 2)] + 1e-12f;
        float2 ag = *(const float2*)&g_agg[r * 64 + c2];
        ag.x /= den; ag.y /= den;
        *(float2*)&xw[c2] = ag;
        __syncwarp();
        u64 sacc = pk2(ns[r * 64 + c2] + Bno[c2], ns[r * 64 + c2 + 1] + Bno[c2 + 1]);
        #pragma unroll 8
        for (int i = 0; i < 64; i++) {
            float xi = xw[i];
            fma2(sacc, pk2(xi, xi), *(const u64*)&Wno[i * 64 + c2]);
        }
        float2 sv = upk2(sacc);
        __syncwarp();
        float s1 = sv.x + sv.y, s2 = sv.x * sv.x + sv.y * sv.y;
        #pragma unroll
        for (int o = 16; o; o >>= 1) {
            s1 += __shfl_xor_sync(0xffffffffu, s1, o);
            s2 += __shfl_xor_sync(0xffffffffu, s2, o);
        }
        float m = s1 * 0.015625f;
        float rs = rsqrtf(s2 * 0.015625f - m * m + 1e-5f);
        xw[c2]     = (sv.x - m) * rs * G[c2] + Bt[c2];
        xw[c2 + 1] = (sv.y - m) * rs * G[c2 + 1] + Bt[c2 + 1];
        __syncwarp();
        u64 h01 = *(const u64*)&B1[c2];
        u64 h23 = *(const u64*)&B1[64 + c2];
        #pragma unroll 8
        for (int i = 0; i < 64; i++) {
            float xi = xw[i];
            u64 xx = pk2(xi, xi);
            fma2(h01, xx, *(const u64*)&W1[i * 128 + c2]);
            fma2(h23, xx, *(const u64*)&W1[i * 128 + 64 + c2]);
        }
        float2 ha = upk2(h01), hb = upk2(h23);
        hw[c2] = fmaxf(ha.x, 0.f); hw[c2 + 1] = fmaxf(ha.y, 0.f);
        hw[64 + c2] = fmaxf(hb.x, 0.f); hw[64 + c2 + 1] = fmaxf(hb.y, 0.f);
        __syncwarp();
        u64 yacc = *(const u64*)&B2[c2];
        #pragma unroll 8
        for (int i = 0; i < 128; i++) {
            float hi = hw[i];
            fma2(yacc, pk2(hi, hi), *(const u64*)&W2[i * 64 + c2]);
        }
        float2 yv = upk2(yacc);
        float2 o; o.x = sv.x + yv.x; o.y = sv.y + yv.y;
        *(float2*)&node_out[r * 64 + c2] = o;
        __syncwarp();
    }
}

// ---------------- K: normalize att (fused) + edge update + edge FFN (tf32 mma) -----------
__global__ __launch_bounds__(512, 1)
void k_edge_ffn_tc(const float* __restrict__ es, float* __restrict__ att,
                   const int* __restrict__ eidx,
                   float* __restrict__ eout,
                   const float* __restrict__ weo, const float* __restrict__ beo,
                   const float* __restrict__ g2, const float* __restrict__ b2,
                   const float* __restrict__ f1w, const float* __restrict__ f1b,
                   const float* __restrict__ f2w, const float* __restrict__ f2b,
                   int E) {
    extern __shared__ float sm[];
    u32*   W1F = (u32*)sm;              // 8192
    u32*   W2F = (u32*)(sm + 8192);     // 8192
    float* B1  = sm + 16384;
    float* B2  = sm + 16512;
    float* G   = sm + 16576;
    float* Bt  = sm + 16640;
    float* WO  = sm + 16704;            // 512
    float* BO  = sm + 17216;            // 64
    float* ES  = sm + 17280;            // 2*8192 (raw es -> in-place x)
    float* AT  = sm + 33664;            // 2*1024 (exp -> normalized in place)
    u32*   XnS = (u32*)(sm + 35712);    // stride 68 (union lo)
    u32*   HS  = (u32*)(sm + 35712);    // stride 132 (union, after sync)
    int tid = threadIdx.x;

    for (int idx = tid; idx < 4096; idx += 512) {
        int L = idx & 31, K = (idx >> 5) & 7, T = idx >> 8;
        int kk = K * 8 + (L & 3), nn = T * 8 + (L >> 2);
        W1F[idx * 2]     = tf32of(f1w[kk * 128 + nn]);
        W1F[idx * 2 + 1] = tf32of(f1w[(kk + 4) * 128 + nn]);
    }
    for (int idx = tid; idx < 4096; idx += 512) {
        int L = idx & 31, K = (idx >> 5) & 15, T = idx >> 9;
        int kk = K * 8 + (L & 3), nn = T * 8 + (L >> 2);
        W2F[idx * 2]     = tf32of(f2w[kk * 64 + nn]);
        W2F[idx * 2 + 1] = tf32of(f2w[(kk + 4) * 64 + nn]);
    }
    if (tid < 512) WO[tid] = weo[tid];
    if (tid < 128) B1[tid] = f1b[tid];
    if (tid < 64) { B2[tid] = f2b[tid]; G[tid] = g2[tid]; Bt[tid] = b2[tid]; BO[tid] = beo[tid]; }
    __syncthreads();

    int warp = tid >> 5, lane = tid & 31;
    int wm = warp & 7, wn = warp >> 3;
    int qr = lane >> 2, qc = lane & 3;
    int r0 = 16 * wm + qr;
    long long ntiles = ((long long)E + 127) >> 7;
    long long stride = gridDim.x;
    u32 es_s0 = (u32)__cvta_generic_to_shared(ES);
    u32 at_s0 = (u32)__cvta_generic_to_shared(AT);

    long long t = blockIdx.x;
    if (t < ntiles) {
        long long base = t << 7;
        #pragma unroll
        for (int j = 0; j < 4; j++) {
            int idx = j * 512 + tid;
            int r = idx >> 4, c4 = (idx & 15) << 2;
            int ok = (base + r) < E ? 16 : 0;
            cp16(es_s0 + (u32)((r * 64 + c4) * 4), &es[(base + r) * 64 + c4], ok);
        }
        if (tid < 256) {
            int ok = (base + (tid >> 1)) < E ? 16 : 0;
            cp16(at_s0 + (u32)(tid * 16), &att[base * 8 + tid * 4], ok);
        }
    }
    CP_COMMIT();

    int pb = 0;
    for (; t < ntiles; t += stride) {
        long long tn = t + stride;
        if (tn < ntiles) {
            long long basen = tn << 7;
            u32 esd = es_s0 + (u32)((pb ^ 1) * 8192 * 4);
            u32 atd = at_s0 + (u32)((pb ^ 1) * 1024 * 4);
            #pragma unroll
            for (int j = 0; j < 4; j++) {
                int idx = j * 512 + tid;
                int r = idx >> 4, c4 = (idx & 15) << 2;
                int ok = (basen + r) < E ? 16 : 0;
                cp16(esd + (u32)((r * 64 + c4) * 4), &es[(basen + r) * 64 + c4], ok);
            }
            if (tid < 256) {
                int ok = (basen + (tid >> 1)) < E ? 16 : 0;
                cp16(atd + (u32)(tid * 16), &att[basen * 8 + tid * 4], ok);
            }
            CP_COMMIT();
            CP_WAIT1();
        } else {
            CP_COMMIT();
            CP_WAIT0();
        }
        __syncthreads();

        long long base = t << 7;
        float* XS = ES + pb * 8192;
        float* ATc = AT + pb * 1024;

        // phase A0 (warp-local rows): normalize att in smem + write back to global
        {
            float* ATw = ATc + warp * 64;
            long long ebase = base + warp * 8;
            #pragma unroll
            for (int j = 0; j < 2; j++) {
                int idx = j * 32 + lane;          // 0..63
                int r = idx >> 3, h = idx & 7;
                long long e = ebase + r;
                if (e < E) {
                    int src = eidx[e];
                    float den = g_ssum[(size_t)src * 8 + h] + 1e-12f;
                    float a = ATw[idx] / den;
                    ATw[idx] = a;
                    att[e * 8 + h] = a;
                }
            }
        }
        __syncwarp();

        // phase A (warp-local rows 8*warp..+7): x = es + att@weo + beo (in place), then LN
        #pragma unroll
        for (int j = 0; j < 4; j++) {
            int idx = j * 32 + lane;                 // 0..127
            int r = warp * 8 + (idx >> 4);
            int c4 = (idx & 15) << 2;
            float4 x = *(float4*)&XS[r * 64 + c4];
            const float* a = &ATc[r * 8];
            float4 u = *(const float4*)&BO[c4];
            #pragma unroll
            for (int h = 0; h < 8; h++) {
                float ah = a[h];
                float4 w = *(const float4*)&WO[h * 64 + c4];
                u.x = fmaf(ah, w.x, u.x); u.y = fmaf(ah, w.y, u.y);
                u.z = fmaf(ah, w.z, u.z); u.w = fmaf(ah, w.w, u.w);
            }
            x.x += u.x; x.y += u.y; x.z += u.z; x.w += u.w;
            *(float4*)&XS[r * 64 + c4] = x;
        }
        __syncwarp();
        for (int r8 = 0; r8 < 8; r8++) {
            int r = warp * 8 + r8;
            float x0 = XS[r * 64 + lane], x1 = XS[r * 64 + lane + 32];
            float s1 = x0 + x1, s2 = x0 * x0 + x1 * x1;
            #pragma unroll
            for (int o = 16; o; o >>= 1) {
                s1 += __shfl_xor_sync(0xffffffffu, s1, o);
                s2 += __shfl_xor_sync(0xffffffffu, s2, o);
            }
            float m = s1 * 0.015625f;
            float rs = rsqrtf(s2 * 0.015625f - m * m + 1e-5f);
            XnS[r * 68 + lane]      = tf32of((x0 - m) * rs * G[lane] + Bt[lane]);
            XnS[r * 68 + lane + 32] = tf32of((x1 - m) * rs * G[lane + 32] + Bt[lane + 32]);
        }
        __syncthreads();
        // GEMM1 (accumulate in regs from XnS)
        float c1[8][4];
        #pragma unroll
        for (int t8 = 0; t8 < 8; t8++) {
            int cc = 64 * wn + 8 * t8 + 2 * qc;
            c1[t8][0] = B1[cc]; c1[t8][1] = B1[cc + 1];
            c1[t8][2] = B1[cc]; c1[t8][3] = B1[cc + 1];
        }
        #pragma unroll
        for (int k = 0; k < 8; k++) {
            u32 a0 = XnS[r0 * 68 + 8 * k + qc];
            u32 a1 = XnS[(r0 + 8) * 68 + 8 * k + qc];
            u32 a2 = XnS[r0 * 68 + 8 * k + qc + 4];
            u32 a3 = XnS[(r0 + 8) * 68 + 8 * k + qc + 4];
            #pragma unroll
            for (int t8 = 0; t8 < 8; t8++) {
                uint2 b = *(const uint2*)&W1F[(((8 * wn + t8) * 8 + k) * 32 + lane) * 2];
                mma_tf32(c1[t8], a0, a1, a2, a3, b.x, b.y);
            }
        }
        __syncthreads();   // XnS fully consumed; HS may overwrite union region
        #pragma unroll
        for (int t8 = 0; t8 < 8; t8++) {
            int cc = 64 * wn + 8 * t8 + 2 * qc;
            uint2 lo, hi;
            lo.x = tf32of(fmaxf(c1[t8][0], 0.f)); lo.y = tf32of(fmaxf(c1[t8][1], 0.f));
            hi.x = tf32of(fmaxf(c1[t8][2], 0.f)); hi.y = tf32of(fmaxf(c1[t8][3], 0.f));
            *(uint2*)&HS[r0 * 132 + cc] = lo;
            *(uint2*)&HS[(r0 + 8) * 132 + cc] = hi;
        }
        __syncthreads();
        // GEMM2 + residual
        float c2[4][4];
        #pragma unroll
        for (int t4 = 0; t4 < 4; t4++) {
            int cc = 32 * wn + 8 * t4 + 2 * qc;
            c2[t4][0] = B2[cc]; c2[t4][1] = B2[cc + 1];
            c2[t4][2] = B2[cc]; c2[t4][3] = B2[cc + 1];
        }
        #pragma unroll
        for (int k = 0; k < 16; k++) {
            u32 a0 = HS[r0 * 132 + 8 * k + qc];
            u32 a1 = HS[(r0 + 8) * 132 + 8 * k + qc];
            u32 a2 = HS[r0 * 132 + 8 * k + qc + 4];
            u32 a3 = HS[(r0 + 8) * 132 + 8 * k + qc + 4];
            #pragma unroll
            for (int t4 = 0; t4 < 4; t4++) {
                uint2 b = *(const uint2*)&W2F[(((4 * wn + t4) * 16 + k) * 32 + lane) * 2];
                mma_tf32(c2[t4], a0, a1, a2, a3, b.x, b.y);
            }
        }
        #pragma unroll
        for (int t4 = 0; t4 < 4; t4++) {
            int cc = 32 * wn + 8 * t4 + 2 * qc;
            long long ro = base + r0;
            if (ro < E) {
                float2 o;
                o.x = XS[r0 * 64 + cc]     + c2[t4][0];
                o.y = XS[r0 * 64 + cc + 1] + c2[t4][1];
                *(float2*)&eout[ro * 64 + cc] = o;
            }
            if (ro + 8 < E) {
                float2 o;
                o.x = XS[(r0 + 8) * 64 + cc]     + c2[t4][2];
                o.y = XS[(r0 + 8) * 64 + cc + 1] + c2[t4][3];
                *(float2*)&eout[(ro + 8) * 64 + cc] = o;
            }
        }
        __syncthreads();
        pb ^= 1;
    }
}

// ---------------- launcher ----------------
extern "C" void kernel_launch(void* const* d_in, const int* in_sizes, int n_in,
                              void* d_out, int out_size) {
    int N = in_sizes[0] / 64;
    int E = in_sizes[1] / 64;

    const int* eidx;
    int base;
    if (in_sizes[2] == 2 * E) { eidx = (const int*)d_in[2]; base = 3; }
    else                      { eidx = (const int*)d_in[n_in - 1]; base = 2; }

    const float* ns = (const float*)d_in[0];
    const float* es = (const float*)d_in[1];
    const float* wq   = (const float*)d_in[base + 0];
    const float* bq   = (const float*)d_in[base + 1];
    const float* wk   = (const float*)d_in[base + 2];
    const float* bk   = (const float*)d_in[base + 3];
    const float* wv   = (const float*)d_in[base + 4];
    const float* bv   = (const float*)d_in[base + 5];
    const float* we   = (const float*)d_in[base + 6];
    const float* be   = (const float*)d_in[base + 7];
    const float* wno  = (const float*)d_in[base + 8];
    const float* bno  = (const float*)d_in[base + 9];
    const float* weo  = (const float*)d_in[base + 10];
    const float* beo  = (const float*)d_in[base + 11];
    const float* n1g  = (const float*)d_in[base + 12];
    const float* n1b  = (const float*)d_in[base + 13];
    const float* e1g  = (const float*)d_in[base + 14];
    const float* e1b  = (const float*)d_in[base + 15];
    const float* n2g  = (const float*)d_in[base + 16];
    const float* n2b  = (const float*)d_in[base + 17];
    const float* e2g  = (const float*)d_in[base + 18];
    const float* e2b  = (const float*)d_in[base + 19];
    const float* nf1w = (const float*)d_in[base + 20];
    const float* nf1b = (const float*)d_in[base + 21];
    const float* nf2w = (const float*)d_in[base + 22];
    const float* nf2b = (const float*)d_in[base + 23];
    const float* ef1w = (const float*)d_in[base + 24];
    const float* ef1b = (const float*)d_in[base + 25];
    const float* ef2w = (const float*)d_in[base + 26];
    const float* ef2b = (const float*)d_in[base + 27];

    float* out      = (float*)d_out;
    float* node_out = out;
    float* edge_out = out + (size_t)N * 64;
    float* att      = edge_out + (size_t)E * 64;

    (void)out_size;

    cudaFuncSetAttribute(k_node_qkv, cudaFuncAttributeMaxDynamicSharedMemorySize, 13120 * 4);
    cudaFuncSetAttribute(k_edge_proj_tc, cudaFuncAttributeMaxDynamicSharedMemorySize, 21184 * 4);
    cudaFuncSetAttribute(k_node_ffn, cudaFuncAttributeMaxDynamicSharedMemorySize, 22400 * 4);
    cudaFuncSetAttribute(k_edge_ffn_tc, cudaFuncAttributeMaxDynamicSharedMemorySize, 52608 * 4);

    // launch order arranged so k_edge_proj_tc is the 4th launch (ncu -s5 -c1 captures it)
    k_init_a<<<(N * 64 + 255) / 256, 256>>>(N);
    k_node_qkv<<<(N + 7) / 8, 256, 13120 * 4>>>(ns, wq, bq, wk, bk, wv, bv, n1g, n1b, N);
    k_init_b<<<(N * 8 + 255) / 256, 256>>>(N);
    k_edge_proj_tc<<<296, 512, 21184 * 4>>>(es, we, be, e1g, e1b, E);
    {
        long long tot = (long long)E * 8;
        k_scores<<<(unsigned)((tot + 255) / 256), 256>>>(eidx, att, E);
    }
    k_node_ffn<<<(N + 7) / 8, 256, 22400 * 4>>>(ns, wno, bno, n2g, n2b,
                                                nf1w, nf1b, nf2w, nf2b, node_out, N);
    k_edge_ffn_tc<<<148, 512, 52608 * 4>>>(es, att, eidx, edge_out, weo, beo, e2g, e2b,
                                           ef1w, ef1b, ef2w, ef2b, E);
}